// round 1
// baseline (speedup 1.0000x reference)
#include <cuda_runtime.h>
#include <math.h>

#define SEQ   512
#define BATCH 128
#define INPD  256
#define HID   1024
#define G4    4096
#define TB    (SEQ*BATCH)   // 65536 rows

// ---- scratch (allocation-free: device globals) ----
__device__ float g_xproj[(size_t)TB * G4];   // 1 GiB: [T*B, 4H]
__device__ float g_hs[(size_t)TB * HID];     // 256 MiB: h per timestep (also the GEMM-A of out-proj)
__device__ float g_c[2][BATCH * HID];        // ping-pong cell state

__device__ __forceinline__ float sigmoidf_(float x) { return 1.0f / (1.0f + expf(-x)); }

// ============================================================================
// Generic fp32 GEMM: C[M,N] = A[M,K] * B[N,K]^T + bias[N]
// Both operands row-major with K contiguous (dot-product form).
// ============================================================================
template<int BM, int BN, int BK, int TM, int TN>
__launch_bounds__(256)
__global__ void gemm_bias_kernel(const float* __restrict__ A,
                                 const float* __restrict__ B,
                                 const float* __restrict__ bias,
                                 float* __restrict__ C,
                                 int M, int N, int K) {
    constexpr int THREADS = (BM / TM) * (BN / TN);
    static_assert(THREADS == 256, "block must be 256 threads");
    constexpr int PAD = 4;
    __shared__ __align__(16) float As[BK][BM + PAD];
    __shared__ __align__(16) float Bs[BK][BN + PAD];

    const int tid  = threadIdx.x;
    const int tx   = tid % (BN / TN);
    const int ty   = tid / (BN / TN);
    const int row0 = blockIdx.y * BM;
    const int col0 = blockIdx.x * BN;

    float acc[TM][TN];
#pragma unroll
    for (int i = 0; i < TM; i++)
#pragma unroll
        for (int j = 0; j < TN; j++) acc[i][j] = 0.0f;

    constexpr int A_LD = BM * BK / (4 * THREADS);
    constexpr int B_LD = BN * BK / (4 * THREADS);
    static_assert(A_LD >= 1 && B_LD >= 1, "tile too small");

    for (int k0 = 0; k0 < K; k0 += BK) {
#pragma unroll
        for (int i = 0; i < A_LD; i++) {
            int idx = tid + i * THREADS;
            int r   = idx / (BK / 4);
            int kq  = idx % (BK / 4);
            float4 v = *(const float4*)(A + (size_t)(row0 + r) * K + k0 + kq * 4);
            As[kq * 4 + 0][r] = v.x; As[kq * 4 + 1][r] = v.y;
            As[kq * 4 + 2][r] = v.z; As[kq * 4 + 3][r] = v.w;
        }
#pragma unroll
        for (int i = 0; i < B_LD; i++) {
            int idx = tid + i * THREADS;
            int r   = idx / (BK / 4);
            int kq  = idx % (BK / 4);
            float4 v = *(const float4*)(B + (size_t)(col0 + r) * K + k0 + kq * 4);
            Bs[kq * 4 + 0][r] = v.x; Bs[kq * 4 + 1][r] = v.y;
            Bs[kq * 4 + 2][r] = v.z; Bs[kq * 4 + 3][r] = v.w;
        }
        __syncthreads();

#pragma unroll
        for (int k = 0; k < BK; k++) {
            float a[TM], b[TN];
#pragma unroll
            for (int i = 0; i < TM; i += 4) {
                float4 v = *(const float4*)&As[k][ty * TM + i];
                a[i] = v.x; a[i + 1] = v.y; a[i + 2] = v.z; a[i + 3] = v.w;
            }
#pragma unroll
            for (int j = 0; j < TN; j += 4) {
                float4 v = *(const float4*)&Bs[k][tx * TN + j];
                b[j] = v.x; b[j + 1] = v.y; b[j + 2] = v.z; b[j + 3] = v.w;
            }
#pragma unroll
            for (int i = 0; i < TM; i++)
#pragma unroll
                for (int j = 0; j < TN; j++) acc[i][j] += a[i] * b[j];
        }
        __syncthreads();
    }

#pragma unroll
    for (int i = 0; i < TM; i++) {
        int r = row0 + ty * TM + i;
#pragma unroll
        for (int j = 0; j < TN; j += 4) {
            int c = col0 + tx * TN + j;
            float4 o;
            o.x = acc[i][j + 0] + bias[c + 0];
            o.y = acc[i][j + 1] + bias[c + 1];
            o.z = acc[i][j + 2] + bias[c + 2];
            o.w = acc[i][j + 3] + bias[c + 3];
            *(float4*)(C + (size_t)r * N + c) = o;
        }
    }
}

// ============================================================================
// One LSTM timestep. Grid: 128 blocks, each covers all 128 batch rows and an
// 8-wide slice of H, computing all 4 gates for that slice (gate columns packed
// per block so each thread owns i,f,g,o of one (b,j) and fuses the activations).
// gates = x_proj[t] + h_{t-1} * Whh^T + bhh ; c,h update ; h -> g_hs[t]
// ============================================================================
__launch_bounds__(256)
__global__ void lstm_step_kernel(int t,
                                 const float* __restrict__ Whh,
                                 const float* __restrict__ bhh) {
    __shared__ __align__(16) float hsm[32][132];  // [k][b], padded
    __shared__ __align__(16) float wsm[32][36];   // [k][l], l = jj*4 + gate

    const int tid = threadIdx.x;
    const int jt  = blockIdx.x;          // H-slice: j = jt*8 .. jt*8+7
    const int tx  = tid & 7;             // jj within slice
    const int ty  = tid >> 3;            // batch group: b = ty*4 .. ty*4+3

    float acc[4][4];                     // [b_i][gate]
#pragma unroll
    for (int i = 0; i < 4; i++)
#pragma unroll
        for (int g = 0; g < 4; g++) acc[i][g] = 0.0f;

    if (t > 0) {
        const float* hprev = g_hs + (size_t)(t - 1) * BATCH * HID;
        const int lw  = tid >> 3;                 // 0..31 : which packed gate-col
        const int kqw = tid & 7;
        const int gw  = lw & 3, jw = lw >> 2;
        const int nw  = gw * HID + jt * 8 + jw;   // global gate column in [0,4H)

        for (int k0 = 0; k0 < HID; k0 += 32) {
            // h tile: 128 b x 32 k  (transpose into [k][b])
#pragma unroll
            for (int i = 0; i < 4; i++) {
                int idx = tid + i * 256;
                int b   = idx >> 3;
                int kq  = idx & 7;
                float4 v = *(const float4*)(hprev + (size_t)b * HID + k0 + kq * 4);
                hsm[kq * 4 + 0][b] = v.x; hsm[kq * 4 + 1][b] = v.y;
                hsm[kq * 4 + 2][b] = v.z; hsm[kq * 4 + 3][b] = v.w;
            }
            // W tile: 32 packed gate-cols x 32 k
            {
                float4 v = *(const float4*)(Whh + (size_t)nw * HID + k0 + kqw * 4);
                wsm[kqw * 4 + 0][lw] = v.x; wsm[kqw * 4 + 1][lw] = v.y;
                wsm[kqw * 4 + 2][lw] = v.z; wsm[kqw * 4 + 3][lw] = v.w;
            }
            __syncthreads();

#pragma unroll
            for (int k = 0; k < 32; k++) {
                float4 av = *(const float4*)&hsm[k][ty * 4];
                float4 wv = *(const float4*)&wsm[k][tx * 4];
                float a[4] = {av.x, av.y, av.z, av.w};
                float w[4] = {wv.x, wv.y, wv.z, wv.w};
#pragma unroll
                for (int i = 0; i < 4; i++)
#pragma unroll
                    for (int g = 0; g < 4; g++) acc[i][g] += a[i] * w[g];
            }
            __syncthreads();
        }
    }

    // epilogue: gates -> activations -> c,h
    const int j = jt * 8 + tx;
    const float* xp = g_xproj + (size_t)t * BATCH * G4;
    const float bi = bhh[j];
    const float bf = bhh[HID + j];
    const float bg = bhh[2 * HID + j];
    const float bo = bhh[3 * HID + j];
    const float* cin  = g_c[t & 1];
    float*       cout = g_c[(t + 1) & 1];
    float*       hout = g_hs + (size_t)t * BATCH * HID;

#pragma unroll
    for (int i = 0; i < 4; i++) {
        int b = ty * 4 + i;
        size_t xb = (size_t)b * G4 + j;
        float gi = acc[i][0] + xp[xb]           + bi;
        float gf = acc[i][1] + xp[xb + HID]     + bf;
        float gg = acc[i][2] + xp[xb + 2 * HID] + bg;
        float go = acc[i][3] + xp[xb + 3 * HID] + bo;
        float cold = (t > 0) ? cin[b * HID + j] : 0.0f;
        float cn = sigmoidf_(gf) * cold + sigmoidf_(gi) * tanhf(gg);
        float hn = sigmoidf_(go) * tanhf(cn);
        cout[b * HID + j] = cn;
        hout[(size_t)b * HID + j] = hn;
    }
}

// ============================================================================
// In-place row-wise log_softmax over 256 columns. One block per row.
// ============================================================================
__launch_bounds__(256)
__global__ void logsoftmax_kernel(float* __restrict__ out) {
    __shared__ float red[256];
    const size_t r = blockIdx.x;
    const int tid  = threadIdx.x;
    float v = out[r * 256 + tid];

    red[tid] = v;
    __syncthreads();
#pragma unroll
    for (int s = 128; s > 0; s >>= 1) {
        if (tid < s) red[tid] = fmaxf(red[tid], red[tid + s]);
        __syncthreads();
    }
    float m = red[0];
    __syncthreads();

    float e = expf(v - m);
    red[tid] = e;
    __syncthreads();
#pragma unroll
    for (int s = 128; s > 0; s >>= 1) {
        if (tid < s) red[tid] += red[tid + s];
        __syncthreads();
    }
    float lse = logf(red[0]) + m;
    out[r * 256 + tid] = v - lse;
}

// ============================================================================
extern "C" void kernel_launch(void* const* d_in, const int* in_sizes, int n_in,
                              void* d_out, int out_size) {
    const float* inp  = (const float*)d_in[0];  // [512,128,256]
    const float* Wxh  = (const float*)d_in[1];  // [4096,256]
    const float* bxh  = (const float*)d_in[2];  // [4096]
    const float* Whh  = (const float*)d_in[3];  // [4096,1024]
    const float* bhh  = (const float*)d_in[4];  // [4096]
    const float* Wout = (const float*)d_in[5];  // [256,1024]
    const float* bout = (const float*)d_in[6];  // [256]
    float* out = (float*)d_out;                 // [512,128,256] fp32

    float* xproj; cudaGetSymbolAddress((void**)&xproj, g_xproj);
    float* hs;    cudaGetSymbolAddress((void**)&hs, g_hs);

    // 1) x_proj[T*B, 4H] = inp @ Wxh^T + bxh
    gemm_bias_kernel<128, 128, 16, 8, 8>
        <<<dim3(G4 / 128, TB / 128), 256>>>(inp, Wxh, bxh, xproj, TB, G4, INPD);

    // 2) recurrence
    for (int t = 0; t < SEQ; t++)
        lstm_step_kernel<<<128, 256>>>(t, Whh, bhh);

    // 3) out[T*B, 256] = hs @ Wout^T + bout
    gemm_bias_kernel<128, 64, 16, 8, 4>
        <<<dim3(INPD / 64, TB / 128), 256>>>(hs, Wout, bout, out, TB, INPD, HID);

    // 4) log_softmax rows
    logsoftmax_kernel<<<TB, 256>>>(out);
}

// round 7
// speedup vs baseline: 1.1225x; 1.1225x over previous
#include <cuda_runtime.h>
#include <math.h>
#include <stdint.h>

#define SEQ   512
#define BATCH 128
#define INPD  256
#define HID   1024
#define G4    4096
#define TB    (SEQ*BATCH)   // 65536 rows

// ---- scratch (allocation-free: device globals) ----
__device__ float g_xproj[(size_t)TB * G4];   // 1 GiB: [T*B, 4H]
__device__ float g_hs[(size_t)TB * HID];     // 256 MiB: h per timestep (fp32)
__device__ float g_c[2][BATCH * HID];        // ping-pong cell state

__device__ __forceinline__ float sigmoidf_(float x) { return 1.0f / (1.0f + expf(-x)); }

// ============================================================================
// tf32 mma helpers (m16n8k8, 3xTF32 fp32-emulation)
// ============================================================================
__device__ __forceinline__ unsigned cvt_tf32(float x) {
    unsigned r;
    asm("cvt.rna.tf32.f32 %0, %1;" : "=r"(r) : "f"(x));
    return r;
}
// hi = tf32(x) (exact as f32 with low mantissa zeroed); lo = tf32(x - hi)
__device__ __forceinline__ void split_tf32(float x, unsigned& hi, unsigned& lo) {
    hi = cvt_tf32(x);
    lo = cvt_tf32(x - __uint_as_float(hi));
}
__device__ __forceinline__ void mma_tf32(float* c, const unsigned* a, const unsigned* b) {
    asm volatile("mma.sync.aligned.m16n8k8.row.col.f32.tf32.tf32.f32 "
        "{%0,%1,%2,%3},{%4,%5,%6,%7},{%8,%9},{%0,%1,%2,%3};"
        : "+f"(c[0]), "+f"(c[1]), "+f"(c[2]), "+f"(c[3])
        : "r"(a[0]), "r"(a[1]), "r"(a[2]), "r"(a[3]), "r"(b[0]), "r"(b[1]));
}

// ============================================================================
// Generic fp32 GEMM: C[M,N] = A[M,K] * B[N,K]^T + bias[N]  (x_proj, out-proj)
// ============================================================================
template<int BM, int BN, int BK, int TM, int TN>
__launch_bounds__(256)
__global__ void gemm_bias_kernel(const float* __restrict__ A,
                                 const float* __restrict__ B,
                                 const float* __restrict__ bias,
                                 float* __restrict__ C,
                                 int M, int N, int K) {
    constexpr int THREADS = (BM / TM) * (BN / TN);
    static_assert(THREADS == 256, "block must be 256 threads");
    constexpr int PAD = 4;
    __shared__ __align__(16) float As[BK][BM + PAD];
    __shared__ __align__(16) float Bs[BK][BN + PAD];

    const int tid  = threadIdx.x;
    const int tx   = tid % (BN / TN);
    const int ty   = tid / (BN / TN);
    const int row0 = blockIdx.y * BM;
    const int col0 = blockIdx.x * BN;

    float acc[TM][TN];
#pragma unroll
    for (int i = 0; i < TM; i++)
#pragma unroll
        for (int j = 0; j < TN; j++) acc[i][j] = 0.0f;

    constexpr int A_LD = BM * BK / (4 * THREADS);
    constexpr int B_LD = BN * BK / (4 * THREADS);

    for (int k0 = 0; k0 < K; k0 += BK) {
#pragma unroll
        for (int i = 0; i < A_LD; i++) {
            int idx = tid + i * THREADS;
            int r   = idx / (BK / 4);
            int kq  = idx % (BK / 4);
            float4 v = *(const float4*)(A + (size_t)(row0 + r) * K + k0 + kq * 4);
            As[kq * 4 + 0][r] = v.x; As[kq * 4 + 1][r] = v.y;
            As[kq * 4 + 2][r] = v.z; As[kq * 4 + 3][r] = v.w;
        }
#pragma unroll
        for (int i = 0; i < B_LD; i++) {
            int idx = tid + i * THREADS;
            int r   = idx / (BK / 4);
            int kq  = idx % (BK / 4);
            float4 v = *(const float4*)(B + (size_t)(col0 + r) * K + k0 + kq * 4);
            Bs[kq * 4 + 0][r] = v.x; Bs[kq * 4 + 1][r] = v.y;
            Bs[kq * 4 + 2][r] = v.z; Bs[kq * 4 + 3][r] = v.w;
        }
        __syncthreads();

#pragma unroll
        for (int k = 0; k < BK; k++) {
            float a[TM], b[TN];
#pragma unroll
            for (int i = 0; i < TM; i += 4) {
                float4 v = *(const float4*)&As[k][ty * TM + i];
                a[i] = v.x; a[i + 1] = v.y; a[i + 2] = v.z; a[i + 3] = v.w;
            }
#pragma unroll
            for (int j = 0; j < TN; j += 4) {
                float4 v = *(const float4*)&Bs[k][tx * TN + j];
                b[j] = v.x; b[j + 1] = v.y; b[j + 2] = v.z; b[j + 3] = v.w;
            }
#pragma unroll
            for (int i = 0; i < TM; i++)
#pragma unroll
                for (int j = 0; j < TN; j++) acc[i][j] += a[i] * b[j];
        }
        __syncthreads();
    }

#pragma unroll
    for (int i = 0; i < TM; i++) {
        int r = row0 + ty * TM + i;
#pragma unroll
        for (int j = 0; j < TN; j += 4) {
            int c = col0 + tx * TN + j;
            float4 o;
            o.x = acc[i][j + 0] + bias[c + 0];
            o.y = acc[i][j + 1] + bias[c + 1];
            o.z = acc[i][j + 2] + bias[c + 2];
            o.w = acc[i][j + 3] + bias[c + 3];
            *(float4*)(C + (size_t)r * N + c) = o;
        }
    }
}

// ============================================================================
// LSTM step via 3xTF32 tensor cores:
//   gates = xproj[t] + h_{t-1} @ Whh^T + bhh
// h and Whh stay fp32 everywhere; tf32 hi/lo operands are built IN REGISTERS
// per fragment (no stored lo planes anywhere).
// Grid: 128 CTAs x 256 threads. CTA = 128 batch rows x 32 packed gate-cols.
// Packed col l (0..31): j = bx*8 + l/4, gate g = l%4.  (mapping validated by
// the hh-only result of R2/R6.)
// 8 warps: warp_m = wid>>1 (m32 slice), warp_n = wid&1 (n16 slice);
// warp tile 32m x 16n = 2 mt x 2 nt of m16n8.
// ============================================================================
#define KC   64
#define APF  68   // fp32 smem pitch (floats): 68 mod 32 = 4 -> conflict-free

__launch_bounds__(256)
__global__ void lstm_step_tf32(int t,
                               const float* __restrict__ Whh,
                               const float* __restrict__ bhh) {
    __shared__ __align__(16) float As[128 * APF];  // h tile, fp32
    __shared__ __align__(16) float Bs[32 * APF];   // Whh tile (packed cols), fp32
    float* gsm = As;                               // [128][34] staging, reuses As

    const int tid    = threadIdx.x;
    const int lane   = tid & 31;
    const int wid    = tid >> 5;
    const int warp_m = wid >> 1;
    const int warp_n = wid & 1;
    const int bx     = blockIdx.x;

    float acc[2][2][4];
#pragma unroll
    for (int i = 0; i < 2; i++)
#pragma unroll
        for (int j = 0; j < 2; j++)
#pragma unroll
            for (int k = 0; k < 4; k++) acc[i][j][k] = 0.0f;

    if (t > 0) {
        const float* hprev = g_hs + (size_t)(t - 1) * BATCH * HID;

        for (int kc = 0; kc < HID; kc += KC) {
            // A tile: 128 rows x 64 cols fp32 (2048 float4s, 8 per thread)
#pragma unroll
            for (int i = 0; i < 8; i++) {
                int idx = tid + i * 256;
                int r = idx >> 4, q = idx & 15;
                *(float4*)&As[r * APF + q * 4] =
                    *(const float4*)(hprev + (size_t)r * HID + kc + q * 4);
            }
            // B tile: 32 packed rows x 64 cols fp32 (512 float4s, 2 per thread)
#pragma unroll
            for (int i = 0; i < 2; i++) {
                int idx = tid + i * 256;
                int r = idx >> 4, q = idx & 15;
                int n_glob = (r & 3) * HID + bx * 8 + (r >> 2);
                *(float4*)&Bs[r * APF + q * 4] =
                    *(const float4*)(Whh + (size_t)n_glob * HID + kc + q * 4);
            }
            __syncthreads();

#pragma unroll
            for (int kk = 0; kk < KC; kk += 8) {
                // A fragments (m16k8): a0=(r,c) a1=(r+8,c) a2=(r,c+4) a3=(r+8,c+4)
                unsigned ahi[2][4], alo[2][4];
#pragma unroll
                for (int mt = 0; mt < 2; mt++) {
                    int row = warp_m * 32 + mt * 16 + (lane >> 2);
                    int c0  = kk + (lane & 3);
                    float f0 = As[row * APF + c0];
                    float f1 = As[(row + 8) * APF + c0];
                    float f2 = As[row * APF + c0 + 4];
                    float f3 = As[(row + 8) * APF + c0 + 4];
                    split_tf32(f0, ahi[mt][0], alo[mt][0]);
                    split_tf32(f1, ahi[mt][1], alo[mt][1]);
                    split_tf32(f2, ahi[mt][2], alo[mt][2]);
                    split_tf32(f3, ahi[mt][3], alo[mt][3]);
                }
                // B fragments (k8n8): b0=(k,n) b1=(k+4,n); smem is Bs[n][k]
                unsigned bhi[2][2], blo[2][2];
#pragma unroll
                for (int nt = 0; nt < 2; nt++) {
                    int brow = warp_n * 16 + nt * 8 + (lane >> 2);
                    int bc   = kk + (lane & 3);
                    float f0 = Bs[brow * APF + bc];
                    float f1 = Bs[brow * APF + bc + 4];
                    split_tf32(f0, bhi[nt][0], blo[nt][0]);
                    split_tf32(f1, bhi[nt][1], blo[nt][1]);
                }
#pragma unroll
                for (int mt = 0; mt < 2; mt++)
#pragma unroll
                    for (int nt = 0; nt < 2; nt++) {
                        mma_tf32(acc[mt][nt], ahi[mt], bhi[nt]);  // hh
                        mma_tf32(acc[mt][nt], ahi[mt], blo[nt]);  // hl
                        mma_tf32(acc[mt][nt], alo[mt], bhi[nt]);  // lh
                    }
            }
            __syncthreads();
        }
    }

    // stage gate pre-activations: gsm[b][l], pitch 34
#pragma unroll
    for (int mt = 0; mt < 2; mt++)
#pragma unroll
        for (int nt = 0; nt < 2; nt++) {
            int row = warp_m * 32 + mt * 16 + (lane >> 2);
            int col = warp_n * 16 + nt * 8 + (lane & 3) * 2;
            *(float2*)(gsm + row * 34 + col) =
                make_float2(acc[mt][nt][0], acc[mt][nt][1]);
            *(float2*)(gsm + (row + 8) * 34 + col) =
                make_float2(acc[mt][nt][2], acc[mt][nt][3]);
        }
    __syncthreads();

    // fused activation epilogue: 1024 (b, jj) items / 256 threads
    const float* xp   = g_xproj + (size_t)t * BATCH * G4;
    const float* cin  = g_c[t & 1];
    float*       cout = g_c[(t + 1) & 1];
    float*       hout = g_hs + (size_t)t * BATCH * HID;

#pragma unroll
    for (int it = 0; it < 4; it++) {
        int item = tid + it * 256;
        int b    = item & 127;
        int jj   = item >> 7;           // 0..7
        int j    = bx * 8 + jj;
        size_t xb = (size_t)b * G4 + j;
        float gi = gsm[b * 34 + jj * 4 + 0] + xp[xb]           + bhh[j];
        float gf = gsm[b * 34 + jj * 4 + 1] + xp[xb + HID]     + bhh[HID + j];
        float gg = gsm[b * 34 + jj * 4 + 2] + xp[xb + 2 * HID] + bhh[2 * HID + j];
        float go = gsm[b * 34 + jj * 4 + 3] + xp[xb + 3 * HID] + bhh[3 * HID + j];
        float cold = (t > 0) ? cin[b * HID + j] : 0.0f;
        float cn = sigmoidf_(gf) * cold + sigmoidf_(gi) * tanhf(gg);
        float hn = sigmoidf_(go) * tanhf(cn);
        cout[b * HID + j] = cn;
        hout[(size_t)b * HID + j] = hn;
    }
}

// ============================================================================
// In-place row-wise log_softmax over 256 columns. One block per row.
// ============================================================================
__launch_bounds__(256)
__global__ void logsoftmax_kernel(float* __restrict__ out) {
    __shared__ float red[256];
    const size_t r = blockIdx.x;
    const int tid  = threadIdx.x;
    float v = out[r * 256 + tid];

    red[tid] = v;
    __syncthreads();
#pragma unroll
    for (int s = 128; s > 0; s >>= 1) {
        if (tid < s) red[tid] = fmaxf(red[tid], red[tid + s]);
        __syncthreads();
    }
    float m = red[0];
    __syncthreads();

    float e = expf(v - m);
    red[tid] = e;
    __syncthreads();
#pragma unroll
    for (int s = 128; s > 0; s >>= 1) {
        if (tid < s) red[tid] += red[tid + s];
        __syncthreads();
    }
    float lse = logf(red[0]) + m;
    out[r * 256 + tid] = v - lse;
}

// ============================================================================
extern "C" void kernel_launch(void* const* d_in, const int* in_sizes, int n_in,
                              void* d_out, int out_size) {
    const float* inp  = (const float*)d_in[0];  // [512,128,256]
    const float* Wxh  = (const float*)d_in[1];  // [4096,256]
    const float* bxh  = (const float*)d_in[2];  // [4096]
    const float* Whh  = (const float*)d_in[3];  // [4096,1024]
    const float* bhh  = (const float*)d_in[4];  // [4096]
    const float* Wout = (const float*)d_in[5];  // [256,1024]
    const float* bout = (const float*)d_in[6];  // [256]
    float* out = (float*)d_out;                 // [512,128,256] fp32

    float* xproj; cudaGetSymbolAddress((void**)&xproj, g_xproj);
    float* hs;    cudaGetSymbolAddress((void**)&hs, g_hs);

    // 1) x_proj[T*B, 4H] = inp @ Wxh^T + bxh  (fp32, known-exact)
    gemm_bias_kernel<128, 128, 16, 8, 8>
        <<<dim3(G4 / 128, TB / 128), 256>>>(inp, Wxh, bxh, xproj, TB, G4, INPD);

    // 2) recurrence (3xTF32 tensor cores; h fp32 end-to-end)
    for (int t = 0; t < SEQ; t++)
        lstm_step_tf32<<<128, 256>>>(t, Whh, bhh);

    // 3) out[T*B, 256] = hs @ Wout^T + bout
    gemm_bias_kernel<128, 64, 16, 8, 4>
        <<<dim3(INPD / 64, TB / 128), 256>>>(hs, Wout, bout, out, TB, INPD, HID);

    // 4) log_softmax rows
    logsoftmax_kernel<<<TB, 256>>>(out);
}

// round 8
// speedup vs baseline: 1.2953x; 1.1540x over previous
#include <cuda_runtime.h>
#include <math.h>
#include <stdint.h>

#define SEQ   512
#define BATCH 128
#define INPD  256
#define HID   1024
#define G4    4096
#define TB    (SEQ*BATCH)   // 65536 rows

// ---- scratch (allocation-free: device globals) ----
__device__ float g_xproj[(size_t)TB * G4];   // 1 GiB: [T*B, 4H]
__device__ float g_hs[(size_t)TB * HID];     // 256 MiB: h per timestep (fp32)
__device__ float g_c[2][BATCH * HID];        // ping-pong cell state

__device__ __forceinline__ float sigmoidf_(float x) { return 1.0f / (1.0f + expf(-x)); }

// ============================================================================
// tf32 mma helpers (m16n8k8, 3xTF32 fp32-emulation) + cp.async
// ============================================================================
__device__ __forceinline__ unsigned smaddr_(const void* p) {
    return (unsigned)__cvta_generic_to_shared(p);
}
__device__ __forceinline__ unsigned cvt_tf32(float x) {
    unsigned r;
    asm("cvt.rna.tf32.f32 %0, %1;" : "=r"(r) : "f"(x));
    return r;
}
__device__ __forceinline__ void split_tf32(float x, unsigned& hi, unsigned& lo) {
    hi = cvt_tf32(x);
    lo = cvt_tf32(x - __uint_as_float(hi));
}
__device__ __forceinline__ void mma_tf32(float* c, const unsigned* a, const unsigned* b) {
    asm volatile("mma.sync.aligned.m16n8k8.row.col.f32.tf32.tf32.f32 "
        "{%0,%1,%2,%3},{%4,%5,%6,%7},{%8,%9},{%0,%1,%2,%3};"
        : "+f"(c[0]), "+f"(c[1]), "+f"(c[2]), "+f"(c[3])
        : "r"(a[0]), "r"(a[1]), "r"(a[2]), "r"(a[3]), "r"(b[0]), "r"(b[1]));
}
__device__ __forceinline__ void cpa16(uint32_t dst, const void* src) {
    asm volatile("cp.async.cg.shared.global [%0], [%1], 16;" :: "r"(dst), "l"(src));
}
#define CPA_COMMIT() asm volatile("cp.async.commit_group;" ::: "memory")
#define CPA_WAIT1()  asm volatile("cp.async.wait_group 1;" ::: "memory")
#define CPA_WAIT0()  asm volatile("cp.async.wait_group 0;" ::: "memory")

extern __shared__ __align__(16) float smemf[];

// ============================================================================
// Generic 3xTF32 GEMM: C[M,N] = A[M,K] * B[N,K]^T + bias[N]
// BM=128, BN=64, KC=64. 256 threads: 8 warps = 4 warp_m (32 rows) x 2 warp_n
// (32 cols); warp tile 32x32 = 2 mt x 4 nt of m16n8. In-register tf32 splits.
// ============================================================================
#define GPITF 68
#define GEMM_SMEM ((128 + 64) * GPITF * 4)   // 52224 bytes

__launch_bounds__(256)
__global__ void gemm_tf32(const float* __restrict__ A,
                          const float* __restrict__ Bm,
                          const float* __restrict__ bias,
                          float* __restrict__ C,
                          int M, int N, int K) {
    float* As = smemf;                 // [128][GPITF]
    float* Bs = smemf + 128 * GPITF;   // [64][GPITF]

    const int tid    = threadIdx.x;
    const int lane   = tid & 31;
    const int wid    = tid >> 5;
    const int warp_m = wid >> 1;
    const int warp_n = wid & 1;
    const int row0   = blockIdx.y * 128;
    const int col0   = blockIdx.x * 64;

    float acc[2][4][4];
#pragma unroll
    for (int i = 0; i < 2; i++)
#pragma unroll
        for (int j = 0; j < 4; j++)
#pragma unroll
            for (int k = 0; k < 4; k++) acc[i][j][k] = 0.0f;

    for (int k0 = 0; k0 < K; k0 += 64) {
        // A tile: 128 rows x 64 floats (2048 float4s / 256 thr = 8 each)
#pragma unroll
        for (int i = 0; i < 8; i++) {
            int idx = tid + i * 256;
            int r = idx >> 4, q = idx & 15;
            *(float4*)&As[r * GPITF + q * 4] =
                *(const float4*)(A + (size_t)(row0 + r) * K + k0 + q * 4);
        }
        // B tile: 64 rows x 64 floats (1024 float4s / 256 thr = 4 each)
#pragma unroll
        for (int i = 0; i < 4; i++) {
            int idx = tid + i * 256;
            int r = idx >> 4, q = idx & 15;
            *(float4*)&Bs[r * GPITF + q * 4] =
                *(const float4*)(Bm + (size_t)(col0 + r) * K + k0 + q * 4);
        }
        __syncthreads();

#pragma unroll
        for (int kk = 0; kk < 64; kk += 8) {
            unsigned ahi[2][4], alo[2][4];
#pragma unroll
            for (int mt = 0; mt < 2; mt++) {
                int row = warp_m * 32 + mt * 16 + (lane >> 2);
                int c0  = kk + (lane & 3);
                split_tf32(As[row * GPITF + c0],           ahi[mt][0], alo[mt][0]);
                split_tf32(As[(row + 8) * GPITF + c0],     ahi[mt][1], alo[mt][1]);
                split_tf32(As[row * GPITF + c0 + 4],       ahi[mt][2], alo[mt][2]);
                split_tf32(As[(row + 8) * GPITF + c0 + 4], ahi[mt][3], alo[mt][3]);
            }
            unsigned bhi[4][2], blo[4][2];
#pragma unroll
            for (int nt = 0; nt < 4; nt++) {
                int brow = warp_n * 32 + nt * 8 + (lane >> 2);
                int bc   = kk + (lane & 3);
                split_tf32(Bs[brow * GPITF + bc],     bhi[nt][0], blo[nt][0]);
                split_tf32(Bs[brow * GPITF + bc + 4], bhi[nt][1], blo[nt][1]);
            }
#pragma unroll
            for (int mt = 0; mt < 2; mt++)
#pragma unroll
                for (int nt = 0; nt < 4; nt++) {
                    mma_tf32(acc[mt][nt], ahi[mt], bhi[nt]);
                    mma_tf32(acc[mt][nt], ahi[mt], blo[nt]);
                    mma_tf32(acc[mt][nt], alo[mt], bhi[nt]);
                }
        }
        __syncthreads();
    }

    // epilogue: C = acc + bias
#pragma unroll
    for (int mt = 0; mt < 2; mt++)
#pragma unroll
        for (int nt = 0; nt < 4; nt++) {
            int row = row0 + warp_m * 32 + mt * 16 + (lane >> 2);
            int col = col0 + warp_n * 32 + nt * 8 + (lane & 3) * 2;
            float b0 = bias[col], b1 = bias[col + 1];
            *(float2*)(C + (size_t)row * N + col) =
                make_float2(acc[mt][nt][0] + b0, acc[mt][nt][1] + b1);
            *(float2*)(C + (size_t)(row + 8) * N + col) =
                make_float2(acc[mt][nt][2] + b0, acc[mt][nt][3] + b1);
        }
}

// ============================================================================
// LSTM step via 3xTF32, cp.async double-buffered (KC=128, 8 chunks).
// Grid: 128 CTAs x 256 threads. CTA = 128 batch rows x 32 packed gate-cols.
// Packed col l (0..31): j = bx*8 + l/4, gate g = l%4  (mapping R7-validated).
// 8 warps: warp_m = wid>>1, warp_n = wid&1; warp tile 32m x 16n.
// ============================================================================
#define KCS   128
#define PITF  132                              // pitch floats, conflict-free
#define STG_F (128 * PITF + 32 * PITF)         // floats per stage: 21120
#define STEP_SMEM (2 * STG_F * 4)              // 168960 bytes

__launch_bounds__(256)
__global__ void lstm_step_tf32(int t,
                               const float* __restrict__ Whh,
                               const float* __restrict__ bhh) {
    const int tid    = threadIdx.x;
    const int lane   = tid & 31;
    const int wid    = tid >> 5;
    const int warp_m = wid >> 1;
    const int warp_n = wid & 1;
    const int bx     = blockIdx.x;

    float* gsm = smemf;   // [128][34] staging, reuses stage 0 after compute

    float acc[2][2][4];
#pragma unroll
    for (int i = 0; i < 2; i++)
#pragma unroll
        for (int j = 0; j < 2; j++)
#pragma unroll
            for (int k = 0; k < 4; k++) acc[i][j][k] = 0.0f;

    if (t > 0) {
        const float* hprev = g_hs + (size_t)(t - 1) * BATCH * HID;

        // issue chunk c's tiles into stage s via cp.async
        auto issue_chunk = [&](int c, int s) {
            const int kc = c * KCS;
            float* As = smemf + s * STG_F;
            float* Bs = As + 128 * PITF;
            // A: 128 rows x 128 floats = 4096 float4s / 256 thr = 16 each
#pragma unroll
            for (int i = 0; i < 16; i++) {
                int idx = tid + i * 256;
                int r = idx >> 5, q = idx & 31;
                cpa16(smaddr_(&As[r * PITF + q * 4]),
                      hprev + (size_t)r * HID + kc + q * 4);
            }
            // B: 32 packed rows x 128 floats = 1024 float4s / 256 thr = 4 each
#pragma unroll
            for (int i = 0; i < 4; i++) {
                int idx = tid + i * 256;
                int r = idx >> 5, q = idx & 31;
                int n_glob = (r & 3) * HID + bx * 8 + (r >> 2);
                cpa16(smaddr_(&Bs[r * PITF + q * 4]),
                      Whh + (size_t)n_glob * HID + kc + q * 4);
            }
        };

        issue_chunk(0, 0);
        CPA_COMMIT();

        for (int c = 0; c < HID / KCS; c++) {
            float* As = smemf + (c & 1) * STG_F;
            float* Bs = As + 128 * PITF;
            if (c + 1 < HID / KCS) {
                issue_chunk(c + 1, (c + 1) & 1);
                CPA_COMMIT();
                CPA_WAIT1();
            } else {
                CPA_WAIT0();
            }
            __syncthreads();

#pragma unroll
            for (int kk = 0; kk < KCS; kk += 8) {
                unsigned ahi[2][4], alo[2][4];
#pragma unroll
                for (int mt = 0; mt < 2; mt++) {
                    int row = warp_m * 32 + mt * 16 + (lane >> 2);
                    int c0  = kk + (lane & 3);
                    split_tf32(As[row * PITF + c0],           ahi[mt][0], alo[mt][0]);
                    split_tf32(As[(row + 8) * PITF + c0],     ahi[mt][1], alo[mt][1]);
                    split_tf32(As[row * PITF + c0 + 4],       ahi[mt][2], alo[mt][2]);
                    split_tf32(As[(row + 8) * PITF + c0 + 4], ahi[mt][3], alo[mt][3]);
                }
                unsigned bhi[2][2], blo[2][2];
#pragma unroll
                for (int nt = 0; nt < 2; nt++) {
                    int brow = warp_n * 16 + nt * 8 + (lane >> 2);
                    int bc   = kk + (lane & 3);
                    split_tf32(Bs[brow * PITF + bc],     bhi[nt][0], blo[nt][0]);
                    split_tf32(Bs[brow * PITF + bc + 4], bhi[nt][1], blo[nt][1]);
                }
#pragma unroll
                for (int mt = 0; mt < 2; mt++)
#pragma unroll
                    for (int nt = 0; nt < 2; nt++) {
                        mma_tf32(acc[mt][nt], ahi[mt], bhi[nt]);
                        mma_tf32(acc[mt][nt], ahi[mt], blo[nt]);
                        mma_tf32(acc[mt][nt], alo[mt], bhi[nt]);
                    }
            }
            __syncthreads();
        }
    }

    // stage gate pre-activations: gsm[b][l], pitch 34
#pragma unroll
    for (int mt = 0; mt < 2; mt++)
#pragma unroll
        for (int nt = 0; nt < 2; nt++) {
            int row = warp_m * 32 + mt * 16 + (lane >> 2);
            int col = warp_n * 16 + nt * 8 + (lane & 3) * 2;
            *(float2*)(gsm + row * 34 + col) =
                make_float2(acc[mt][nt][0], acc[mt][nt][1]);
            *(float2*)(gsm + (row + 8) * 34 + col) =
                make_float2(acc[mt][nt][2], acc[mt][nt][3]);
        }
    __syncthreads();

    // fused activation epilogue: 1024 (b, jj) items / 256 threads
    const float* xp   = g_xproj + (size_t)t * BATCH * G4;
    const float* cin  = g_c[t & 1];
    float*       cout = g_c[(t + 1) & 1];
    float*       hout = g_hs + (size_t)t * BATCH * HID;

#pragma unroll
    for (int it = 0; it < 4; it++) {
        int item = tid + it * 256;
        int b    = item & 127;
        int jj   = item >> 7;           // 0..7
        int j    = bx * 8 + jj;
        size_t xb = (size_t)b * G4 + j;
        float gi = gsm[b * 34 + jj * 4 + 0] + xp[xb]           + bhh[j];
        float gf = gsm[b * 34 + jj * 4 + 1] + xp[xb + HID]     + bhh[HID + j];
        float gg = gsm[b * 34 + jj * 4 + 2] + xp[xb + 2 * HID] + bhh[2 * HID + j];
        float go = gsm[b * 34 + jj * 4 + 3] + xp[xb + 3 * HID] + bhh[3 * HID + j];
        float cold = (t > 0) ? cin[b * HID + j] : 0.0f;
        float cn = sigmoidf_(gf) * cold + sigmoidf_(gi) * tanhf(gg);
        float hn = sigmoidf_(go) * tanhf(cn);
        cout[b * HID + j] = cn;
        hout[(size_t)b * HID + j] = hn;
    }
}

// ============================================================================
// In-place row-wise log_softmax over 256 columns. One block per row.
// ============================================================================
__launch_bounds__(256)
__global__ void logsoftmax_kernel(float* __restrict__ out) {
    __shared__ float red[256];
    const size_t r = blockIdx.x;
    const int tid  = threadIdx.x;
    float v = out[r * 256 + tid];

    red[tid] = v;
    __syncthreads();
#pragma unroll
    for (int s = 128; s > 0; s >>= 1) {
        if (tid < s) red[tid] = fmaxf(red[tid], red[tid + s]);
        __syncthreads();
    }
    float m = red[0];
    __syncthreads();

    float e = expf(v - m);
    red[tid] = e;
    __syncthreads();
#pragma unroll
    for (int s = 128; s > 0; s >>= 1) {
        if (tid < s) red[tid] += red[tid + s];
        __syncthreads();
    }
    float lse = logf(red[0]) + m;
    out[r * 256 + tid] = v - lse;
}

// ============================================================================
extern "C" void kernel_launch(void* const* d_in, const int* in_sizes, int n_in,
                              void* d_out, int out_size) {
    const float* inp  = (const float*)d_in[0];  // [512,128,256]
    const float* Wxh  = (const float*)d_in[1];  // [4096,256]
    const float* bxh  = (const float*)d_in[2];  // [4096]
    const float* Whh  = (const float*)d_in[3];  // [4096,1024]
    const float* bhh  = (const float*)d_in[4];  // [4096]
    const float* Wout = (const float*)d_in[5];  // [256,1024]
    const float* bout = (const float*)d_in[6];  // [256]
    float* out = (float*)d_out;                 // [512,128,256] fp32

    float* xproj; cudaGetSymbolAddress((void**)&xproj, g_xproj);
    float* hs;    cudaGetSymbolAddress((void**)&hs, g_hs);

    cudaFuncSetAttribute(lstm_step_tf32,
                         cudaFuncAttributeMaxDynamicSharedMemorySize, STEP_SMEM);
    cudaFuncSetAttribute(gemm_tf32,
                         cudaFuncAttributeMaxDynamicSharedMemorySize, GEMM_SMEM);

    // 1) x_proj[T*B, 4H] = inp @ Wxh^T + bxh  (3xTF32 tensor cores)
    gemm_tf32<<<dim3(G4 / 64, TB / 128), 256, GEMM_SMEM>>>(
        inp, Wxh, bxh, xproj, TB, G4, INPD);

    // 2) recurrence (3xTF32 tensor cores, cp.async double-buffered)
    for (int t = 0; t < SEQ; t++)
        lstm_step_tf32<<<128, 256, STEP_SMEM>>>(t, Whh, bhh);

    // 3) out[T*B, 256] = hs @ Wout^T + bout  (3xTF32 tensor cores)
    gemm_tf32<<<dim3(INPD / 64, TB / 128), 256, GEMM_SMEM>>>(
        hs, Wout, bout, out, TB, INPD, HID);

    // 4) log_softmax rows
    logsoftmax_kernel<<<TB, 256>>>(out);
}